// round 5
// baseline (speedup 1.0000x reference)
#include <cuda_runtime.h>
#include <cstdint>

#define Cc 64
#define CO 64
#define Ss 256
#define LL (Ss * Ss)

// ---------------------------------------------------------------------------
// Fully fused Reverb kernel.
//   g[c,l]   = x[c,l] * sum_{i,j valid} w[c*9+i*3+j, (y+1-i)*S + (x+1-j)]
//   out[o,l] = sum_c conv[c,o] * g[c,l]
// Each block owns 128 consecutive pixels (half an image row).
// Phase 1 (per c-chunk of 32): tap-gather g into smem (coalesced float4).
// Phase 2: channel mix from smem; conv pre-duplicated as packed (v,v) pairs
// so the inner loop is LDS.128 + fma.rn.f32x2 only (no packing movs).
// ---------------------------------------------------------------------------
__global__ __launch_bounds__(256, 3) void reverb_fused_kernel(
    const float* __restrict__ x,      // (C, L)
    const float* __restrict__ w,      // (C*9, L)
    const float* __restrict__ conv,   // (C, CO)
    float* __restrict__ out)          // (CO, L)
{
    __shared__ float sg[32 * 128];                    // 16 KB: g chunk [32c][128px]
    __shared__ unsigned long long sconv2[Cc * CO];    // 32 KB: dup-pair conv table

    const int tid = threadIdx.x;

    // Build duplicated conv table: sconv2[c*64+o] = {conv[c,o], conv[c,o]}
    for (int i = tid; i < Cc * CO; i += 256) {
        const float v = conv[i];
        unsigned long long d;
        asm("mov.b64 %0, {%1, %1};" : "=l"(d) : "f"(v));
        sconv2[i] = d;
    }

    const int lbase = blockIdx.x * 128;   // 128 pixels, all in one image row
    const int yb = lbase >> 8;
    const int xb = lbase & 255;

    const int og = tid >> 5;              // warp id -> output group (8 outputs)
    const int lane = tid & 31;

    unsigned long long acc[8][2];         // [o within group][pixel pair]
#pragma unroll
    for (int o = 0; o < 8; o++) { acc[o][0] = 0ull; acc[o][1] = 0ull; }

    for (int r = 0; r < 2; r++) {         // c-chunks of 32
        // ---- Phase 1: tap-gather 32 channels x 128 px into sg ----
#pragma unroll 2
        for (int k = 0; k < 4; k++) {
            const int gid = k * 256 + tid;          // 0..1023
            const int cl = gid >> 5;                // 0..31 (chunk-local c)
            const int c = r * 32 + cl;
            const int grp = gid & 31;
            const int x0 = xb + grp * 4;

            const float* wc = w + (size_t)c * 9 * LL;

            const float mL = (x0 == 0) ? 0.0f : 1.0f;
            const float mR = (x0 == Ss - 4) ? 0.0f : 1.0f;
            const int xL = (x0 == 0) ? 0 : x0 - 1;
            const int xR = (x0 == Ss - 4) ? Ss - 1 : x0 + 4;

            float ws0 = 0.f, ws1 = 0.f, ws2 = 0.f, ws3 = 0.f;
#pragma unroll
            for (int i = 0; i < 3; i++) {
                const int ry = yb + 1 - i;
                const bool vy = (unsigned)ry < (unsigned)Ss;
                const float my = vy ? 1.0f : 0.0f;
                const int ryc = vy ? ry : yb;
                const int rowoff = ryc * Ss + x0;

                const float* p0 = wc + (size_t)(i * 3 + 0) * LL + rowoff;
                const float* p1 = wc + (size_t)(i * 3 + 1) * LL + rowoff;
                const float* p2 = wc + (size_t)(i * 3 + 2) * LL + rowoff;

                const float4 a = __ldg((const float4*)p0);
                const float  rsc = mR * __ldg(p0 - x0 + xR);
                const float4 b = __ldg((const float4*)p1);
                const float  lsc = mL * __ldg(p2 - x0 + xL);
                const float4 d = __ldg((const float4*)p2);

                ws0 = fmaf(my, (a.y + b.x) + lsc, ws0);
                ws1 = fmaf(my, (a.z + b.y) + d.x, ws1);
                ws2 = fmaf(my, (a.w + b.z) + d.y, ws2);
                ws3 = fmaf(my, (rsc + b.w) + d.z, ws3);
            }

            const float4 xv = __ldg((const float4*)(x + (size_t)c * LL + lbase + grp * 4));
            float4 gv;
            gv.x = xv.x * ws0;
            gv.y = xv.y * ws1;
            gv.z = xv.z * ws2;
            gv.w = xv.w * ws3;
            *(float4*)(sg + cl * 128 + grp * 4) = gv;
        }
        __syncthreads();   // g chunk ready (also covers conv2 build on r==0)

        // ---- Phase 2: channel mix for this chunk ----
#pragma unroll 4
        for (int cl = 0; cl < 32; cl++) {
            // g pixel pairs: 4 px as 2 packed f32x2 straight from LDS.128
            const ulonglong2 g2 = *(const ulonglong2*)(sg + cl * 128 + lane * 4);
            // conv dup pairs for this warp's 8 outputs (broadcast LDS.128)
            const ulonglong2* cv =
                (const ulonglong2*)(sconv2 + (r * 32 + cl) * CO + og * 8);
            const ulonglong2 c01 = cv[0];
            const ulonglong2 c23 = cv[1];
            const ulonglong2 c45 = cv[2];
            const ulonglong2 c67 = cv[3];

            asm("fma.rn.f32x2 %0, %1, %2, %0;" : "+l"(acc[0][0]) : "l"(c01.x), "l"(g2.x));
            asm("fma.rn.f32x2 %0, %1, %2, %0;" : "+l"(acc[0][1]) : "l"(c01.x), "l"(g2.y));
            asm("fma.rn.f32x2 %0, %1, %2, %0;" : "+l"(acc[1][0]) : "l"(c01.y), "l"(g2.x));
            asm("fma.rn.f32x2 %0, %1, %2, %0;" : "+l"(acc[1][1]) : "l"(c01.y), "l"(g2.y));
            asm("fma.rn.f32x2 %0, %1, %2, %0;" : "+l"(acc[2][0]) : "l"(c23.x), "l"(g2.x));
            asm("fma.rn.f32x2 %0, %1, %2, %0;" : "+l"(acc[2][1]) : "l"(c23.x), "l"(g2.y));
            asm("fma.rn.f32x2 %0, %1, %2, %0;" : "+l"(acc[3][0]) : "l"(c23.y), "l"(g2.x));
            asm("fma.rn.f32x2 %0, %1, %2, %0;" : "+l"(acc[3][1]) : "l"(c23.y), "l"(g2.y));
            asm("fma.rn.f32x2 %0, %1, %2, %0;" : "+l"(acc[4][0]) : "l"(c45.x), "l"(g2.x));
            asm("fma.rn.f32x2 %0, %1, %2, %0;" : "+l"(acc[4][1]) : "l"(c45.x), "l"(g2.y));
            asm("fma.rn.f32x2 %0, %1, %2, %0;" : "+l"(acc[5][0]) : "l"(c45.y), "l"(g2.x));
            asm("fma.rn.f32x2 %0, %1, %2, %0;" : "+l"(acc[5][1]) : "l"(c45.y), "l"(g2.y));
            asm("fma.rn.f32x2 %0, %1, %2, %0;" : "+l"(acc[6][0]) : "l"(c67.x), "l"(g2.x));
            asm("fma.rn.f32x2 %0, %1, %2, %0;" : "+l"(acc[6][1]) : "l"(c67.x), "l"(g2.y));
            asm("fma.rn.f32x2 %0, %1, %2, %0;" : "+l"(acc[7][0]) : "l"(c67.y), "l"(g2.x));
            asm("fma.rn.f32x2 %0, %1, %2, %0;" : "+l"(acc[7][1]) : "l"(c67.y), "l"(g2.y));
        }
        __syncthreads();   // done reading sg before next chunk overwrites it
    }

    // ---- Epilogue: 8 coalesced STG.128 per warp ----
#pragma unroll
    for (int o = 0; o < 8; o++) {
        unsigned int p0, p1, p2, p3;
        asm("mov.b64 {%0, %1}, %2;" : "=r"(p0), "=r"(p1) : "l"(acc[o][0]));
        asm("mov.b64 {%0, %1}, %2;" : "=r"(p2), "=r"(p3) : "l"(acc[o][1]));
        float4 v;
        v.x = __uint_as_float(p0);
        v.y = __uint_as_float(p1);
        v.z = __uint_as_float(p2);
        v.w = __uint_as_float(p3);
        *(float4*)(out + (size_t)(og * 8 + o) * LL + lbase + lane * 4) = v;
    }
}

extern "C" void kernel_launch(void* const* d_in, const int* in_sizes, int n_in,
                              void* d_out, int out_size) {
    const float* x    = (const float*)d_in[0];  // (1, C, S, S)
    const float* w    = (const float*)d_in[1];  // (1, C*9, L)
    const float* conv = (const float*)d_in[2];  // (C, CO)
    float* out = (float*)d_out;                 // (1, CO, S, S)

    reverb_fused_kernel<<<LL / 128, 256>>>(x, w, conv, out);
}

// round 6
// speedup vs baseline: 1.2485x; 1.2485x over previous
#include <cuda_runtime.h>
#include <cstdint>

#define Cc 64
#define CO 64
#define Ss 256
#define LL (Ss * Ss)

// 16 MB scratch for g[c,l] = x[c,l] * Wsum[c,l]
__device__ float g_scratch[Cc * LL];

// ---------------------------------------------------------------------------
// Kernel A: tap-gather, 4 pixels per thread, vectorized float4 loads.
// g[c,y,x] = x[c,y,x] * sum_{i,j valid} w[c*9 + i*3+j, (y+1-i)*S + (x+1-j)]
// ---------------------------------------------------------------------------
__global__ __launch_bounds__(256) void reverb_gather_kernel(
    const float* __restrict__ x,   // (C, L)
    const float* __restrict__ w)   // (C*9, L)
{
    const int t = blockIdx.x * 256 + threadIdx.x;   // 0 .. C*L/4-1
    const int c = t >> 14;                          // LL/4 = 16384 groups/channel
    const int q = t & 16383;
    const int y  = q >> 6;
    const int x0 = (q & 63) << 2;

    const float* wc = w + (size_t)c * 9 * LL;

    const float mL = (x0 == 0)        ? 0.0f : 1.0f;
    const float mR = (x0 == Ss - 4)   ? 0.0f : 1.0f;
    const int xL = (x0 == 0) ? 0 : x0 - 1;
    const int xR = (x0 == Ss - 4) ? Ss - 1 : x0 + 4;

    float ws0 = 0.f, ws1 = 0.f, ws2 = 0.f, ws3 = 0.f;

#pragma unroll
    for (int i = 0; i < 3; i++) {
        const int ry = y + 1 - i;
        const bool vy = (unsigned)ry < (unsigned)Ss;
        const float my = vy ? 1.0f : 0.0f;
        const int ryc = vy ? ry : y;
        const int rowoff = ryc * Ss + x0;

        const float* p0 = wc + (size_t)(i * 3 + 0) * LL + rowoff;
        const float* p1 = wc + (size_t)(i * 3 + 1) * LL + rowoff;
        const float* p2 = wc + (size_t)(i * 3 + 2) * LL + rowoff;

        const float4 a = __ldg((const float4*)p0);
        const float  rsc = mR * __ldg(p0 - x0 + xR);
        const float4 b = __ldg((const float4*)p1);
        const float  lsc = mL * __ldg(p2 - x0 + xL);
        const float4 d = __ldg((const float4*)p2);

        ws0 = fmaf(my, (a.y + b.x) + lsc, ws0);
        ws1 = fmaf(my, (a.z + b.y) + d.x, ws1);
        ws2 = fmaf(my, (a.w + b.z) + d.y, ws2);
        ws3 = fmaf(my, (rsc + b.w) + d.z, ws3);
    }

    const float4 xv = __ldg((const float4*)(x + (size_t)t * 4));
    float4 gv;
    gv.x = xv.x * ws0;
    gv.y = xv.y * ws1;
    gv.z = xv.z * ws2;
    gv.w = xv.w * ws3;
    *((float4*)(g_scratch + (size_t)t * 4)) = gv;
}

// ---------------------------------------------------------------------------
// Kernel B: channel mix. out[o,l] = sum_c conv[c,o] * g[c,l]
// Block owns 128 pixels. Load phase: 8 independent coalesced LDG.128/thread
// stage g[64c x 128px] (32 KB) into smem (front-batched -> high MLP). One
// sync, then compute: per c-iter per warp 1 lane-varying LDS.128 (4 px as 2
// packed f32x2) + 4 broadcast LDS.128 (conv dup-pairs) + 16 FFMA2.
// ---------------------------------------------------------------------------
__global__ __launch_bounds__(256, 3) void reverb_mix_kernel(
    const float* __restrict__ conv,   // (C, CO)
    float* __restrict__ out)          // (CO, L)
{
    __shared__ unsigned long long sconv2[Cc * CO];  // 32 KB dup-pair conv
    __shared__ float sg[Cc * 128];                  // 32 KB g block

    const int tid = threadIdx.x;

    // Build duplicated conv table: sconv2[c*64+o] = {conv[c,o], conv[c,o]}
    for (int i = tid; i < Cc * CO; i += 256) {
        const float v = conv[i];
        unsigned long long d;
        asm("mov.b64 %0, {%1, %1};" : "=l"(d) : "f"(v));
        sconv2[i] = d;
    }

    const int lbase = blockIdx.x * 128;

    // ---- Load phase: front-batched, fully coalesced ----
    {
        float4 tmp[8];
#pragma unroll
        for (int k = 0; k < 8; k++) {
            const int slot = tid + 256 * k;       // 0..2047 float4 slots
            const int c = slot >> 5;              // 32 float4 per channel row
            const int grp = slot & 31;
            tmp[k] = *(const float4*)(g_scratch + (size_t)c * LL + lbase + grp * 4);
        }
#pragma unroll
        for (int k = 0; k < 8; k++) {
            const int slot = tid + 256 * k;
            *(float4*)(sg + slot * 4) = tmp[k];
        }
    }
    __syncthreads();

    // ---- Compute phase ----
    const int og   = tid >> 5;          // warp id -> 8 outputs [8og, 8og+8)
    const int lane = tid & 31;

    unsigned long long acc[8][2];       // [o within group][pixel pair]
#pragma unroll
    for (int o = 0; o < 8; o++) { acc[o][0] = 0ull; acc[o][1] = 0ull; }

#pragma unroll 8
    for (int c = 0; c < Cc; c++) {
        const ulonglong2 g2 = *(const ulonglong2*)(sg + c * 128 + lane * 4);
        const ulonglong2* cv = (const ulonglong2*)(sconv2 + c * CO + og * 8);
        const ulonglong2 c01 = cv[0];
        const ulonglong2 c23 = cv[1];
        const ulonglong2 c45 = cv[2];
        const ulonglong2 c67 = cv[3];

        asm("fma.rn.f32x2 %0, %1, %2, %0;" : "+l"(acc[0][0]) : "l"(c01.x), "l"(g2.x));
        asm("fma.rn.f32x2 %0, %1, %2, %0;" : "+l"(acc[0][1]) : "l"(c01.x), "l"(g2.y));
        asm("fma.rn.f32x2 %0, %1, %2, %0;" : "+l"(acc[1][0]) : "l"(c01.y), "l"(g2.x));
        asm("fma.rn.f32x2 %0, %1, %2, %0;" : "+l"(acc[1][1]) : "l"(c01.y), "l"(g2.y));
        asm("fma.rn.f32x2 %0, %1, %2, %0;" : "+l"(acc[2][0]) : "l"(c23.x), "l"(g2.x));
        asm("fma.rn.f32x2 %0, %1, %2, %0;" : "+l"(acc[2][1]) : "l"(c23.x), "l"(g2.y));
        asm("fma.rn.f32x2 %0, %1, %2, %0;" : "+l"(acc[3][0]) : "l"(c23.y), "l"(g2.x));
        asm("fma.rn.f32x2 %0, %1, %2, %0;" : "+l"(acc[3][1]) : "l"(c23.y), "l"(g2.y));
        asm("fma.rn.f32x2 %0, %1, %2, %0;" : "+l"(acc[4][0]) : "l"(c45.x), "l"(g2.x));
        asm("fma.rn.f32x2 %0, %1, %2, %0;" : "+l"(acc[4][1]) : "l"(c45.x), "l"(g2.y));
        asm("fma.rn.f32x2 %0, %1, %2, %0;" : "+l"(acc[5][0]) : "l"(c45.y), "l"(g2.x));
        asm("fma.rn.f32x2 %0, %1, %2, %0;" : "+l"(acc[5][1]) : "l"(c45.y), "l"(g2.y));
        asm("fma.rn.f32x2 %0, %1, %2, %0;" : "+l"(acc[6][0]) : "l"(c67.x), "l"(g2.x));
        asm("fma.rn.f32x2 %0, %1, %2, %0;" : "+l"(acc[6][1]) : "l"(c67.x), "l"(g2.y));
        asm("fma.rn.f32x2 %0, %1, %2, %0;" : "+l"(acc[7][0]) : "l"(c67.y), "l"(g2.x));
        asm("fma.rn.f32x2 %0, %1, %2, %0;" : "+l"(acc[7][1]) : "l"(c67.y), "l"(g2.y));
    }

    // ---- Epilogue: 8 coalesced STG.128 per warp ----
#pragma unroll
    for (int o = 0; o < 8; o++) {
        unsigned int p0, p1, p2, p3;
        asm("mov.b64 {%0, %1}, %2;" : "=r"(p0), "=r"(p1) : "l"(acc[o][0]));
        asm("mov.b64 {%0, %1}, %2;" : "=r"(p2), "=r"(p3) : "l"(acc[o][1]));
        float4 v;
        v.x = __uint_as_float(p0);
        v.y = __uint_as_float(p1);
        v.z = __uint_as_float(p2);
        v.w = __uint_as_float(p3);
        *(float4*)(out + (size_t)(og * 8 + o) * LL + lbase + lane * 4) = v;
    }
}

extern "C" void kernel_launch(void* const* d_in, const int* in_sizes, int n_in,
                              void* d_out, int out_size) {
    const float* x    = (const float*)d_in[0];  // (1, C, S, S)
    const float* w    = (const float*)d_in[1];  // (1, C*9, L)
    const float* conv = (const float*)d_in[2];  // (C, CO)
    float* out = (float*)d_out;                 // (1, CO, S, S)

    reverb_gather_kernel<<<(Cc * LL / 4) / 256, 256>>>(x, w);
    reverb_mix_kernel<<<LL / 128, 256>>>(conv, out);
}

// round 8
// speedup vs baseline: 1.4536x; 1.1643x over previous
#include <cuda_runtime.h>
#include <cstdint>

#define Cc 64
#define CO 64
#define Ss 256
#define LL (Ss * Ss)

// 16 MB scratch for g[c,l] = x[c,l] * Wsum[c,l]
__device__ float g_scratch[Cc * LL];

// ---------------------------------------------------------------------------
// Kernel A: tap-gather, 4 pixels per thread, vectorized float4 loads.
// g[c,y,x] = x[c,y,x] * sum_{i,j valid} w[c*9 + i*3+j, (y+1-i)*S + (x+1-j)]
// ---------------------------------------------------------------------------
__global__ __launch_bounds__(256) void reverb_gather_kernel(
    const float* __restrict__ x,   // (C, L)
    const float* __restrict__ w)   // (C*9, L)
{
    const int t = blockIdx.x * 256 + threadIdx.x;   // 0 .. C*L/4-1
    const int c = t >> 14;                          // LL/4 = 16384 groups/channel
    const int q = t & 16383;
    const int y  = q >> 6;
    const int x0 = (q & 63) << 2;

    const float* wc = w + (size_t)c * 9 * LL;

    const float mL = (x0 == 0)        ? 0.0f : 1.0f;
    const float mR = (x0 == Ss - 4)   ? 0.0f : 1.0f;
    const int xL = (x0 == 0) ? 0 : x0 - 1;
    const int xR = (x0 == Ss - 4) ? Ss - 1 : x0 + 4;

    float ws0 = 0.f, ws1 = 0.f, ws2 = 0.f, ws3 = 0.f;

#pragma unroll
    for (int i = 0; i < 3; i++) {
        const int ry = y + 1 - i;
        const bool vy = (unsigned)ry < (unsigned)Ss;
        const float my = vy ? 1.0f : 0.0f;
        const int ryc = vy ? ry : y;
        const int rowoff = ryc * Ss + x0;

        const float* p0 = wc + (size_t)(i * 3 + 0) * LL + rowoff;
        const float* p1 = wc + (size_t)(i * 3 + 1) * LL + rowoff;
        const float* p2 = wc + (size_t)(i * 3 + 2) * LL + rowoff;

        const float4 a = __ldg((const float4*)p0);
        const float  rsc = mR * __ldg(p0 - x0 + xR);
        const float4 b = __ldg((const float4*)p1);
        const float  lsc = mL * __ldg(p2 - x0 + xL);
        const float4 d = __ldg((const float4*)p2);

        ws0 = fmaf(my, (a.y + b.x) + lsc, ws0);
        ws1 = fmaf(my, (a.z + b.y) + d.x, ws1);
        ws2 = fmaf(my, (a.w + b.z) + d.y, ws2);
        ws3 = fmaf(my, (rsc + b.w) + d.z, ws3);
    }

    const float4 xv = __ldg((const float4*)(x + (size_t)t * 4));
    float4 gv;
    gv.x = xv.x * ws0;
    gv.y = xv.y * ws1;
    gv.z = xv.z * ws2;
    gv.w = xv.w * ws3;
    *((float4*)(g_scratch + (size_t)t * 4)) = gv;
}

// ---------------------------------------------------------------------------
// Kernel B: channel mix. out[o,l] = sum_c conv[c,o] * g[c,l]
// Block owns 128 pixels; 8 warps, warp og owns outputs [8og, 8og+8).
// smem: sg 32 KB (g block) + sconv 16 KB (natural layout) = 48 KB -> 4 blk/SM.
// Accumulators packed along o: acc[op][p] = {out[2op][px p], out[2op+1][px p]}
// so conv pairs load as ulonglong2 directly (no dup table, no conv movs);
// g values duplicated with 4 movs/c.
// ---------------------------------------------------------------------------
__global__ __launch_bounds__(256, 4) void reverb_mix_kernel(
    const float* __restrict__ conv,   // (C, CO)
    float* __restrict__ out)          // (CO, L)
{
    __shared__ float sconv[Cc * CO];  // 16 KB natural layout
    __shared__ float sg[Cc * 128];    // 32 KB g block

    const int tid = threadIdx.x;
    const int lbase = blockIdx.x * 128;

    // Load conv table (16 KB = 4 float4 per thread)
#pragma unroll
    for (int k = 0; k < 4; k++) {
        const int i = tid + 256 * k;
        ((float4*)sconv)[i] = ((const float4*)conv)[i];
    }

    // ---- Load phase: g block, front-batched, fully coalesced ----
    {
        float4 tmp[8];
#pragma unroll
        for (int k = 0; k < 8; k++) {
            const int slot = tid + 256 * k;       // 0..2047 float4 slots
            const int c = slot >> 5;              // 32 float4 per channel row
            const int grp = slot & 31;
            tmp[k] = *(const float4*)(g_scratch + (size_t)c * LL + lbase + grp * 4);
        }
#pragma unroll
        for (int k = 0; k < 8; k++) {
            const int slot = tid + 256 * k;
            *(float4*)(sg + slot * 4) = tmp[k];
        }
    }
    __syncthreads();

    // ---- Compute phase ----
    const int og   = tid >> 5;          // warp id -> 8 outputs [8og, 8og+8)
    const int lane = tid & 31;

    unsigned long long acc[4][4];       // [o-pair][pixel]
#pragma unroll
    for (int op = 0; op < 4; op++)
#pragma unroll
        for (int p = 0; p < 4; p++) acc[op][p] = 0ull;

#pragma unroll 4
    for (int c = 0; c < Cc; c++) {
        const float4 g4 = *(const float4*)(sg + c * 128 + lane * 4);
        unsigned long long gp[4];
        asm("mov.b64 %0, {%1, %1};" : "=l"(gp[0]) : "f"(g4.x));
        asm("mov.b64 %0, {%1, %1};" : "=l"(gp[1]) : "f"(g4.y));
        asm("mov.b64 %0, {%1, %1};" : "=l"(gp[2]) : "f"(g4.z));
        asm("mov.b64 %0, {%1, %1};" : "=l"(gp[3]) : "f"(g4.w));

        // conv pairs {conv[c,o], conv[c,o+1]} direct from smem (broadcast)
        const ulonglong2* cv = (const ulonglong2*)(sconv + c * CO + og * 8);
        const ulonglong2 cva = cv[0];   // pairs (0,1) and (2,3)
        const ulonglong2 cvb = cv[1];   // pairs (4,5) and (6,7)

#pragma unroll
        for (int p = 0; p < 4; p++) {
            asm("fma.rn.f32x2 %0, %1, %2, %0;" : "+l"(acc[0][p]) : "l"(cva.x), "l"(gp[p]));
            asm("fma.rn.f32x2 %0, %1, %2, %0;" : "+l"(acc[1][p]) : "l"(cva.y), "l"(gp[p]));
            asm("fma.rn.f32x2 %0, %1, %2, %0;" : "+l"(acc[2][p]) : "l"(cvb.x), "l"(gp[p]));
            asm("fma.rn.f32x2 %0, %1, %2, %0;" : "+l"(acc[3][p]) : "l"(cvb.y), "l"(gp[p]));
        }
    }

    // ---- Epilogue: unpack, 8 coalesced STG.128 per warp ----
#pragma unroll
    for (int op = 0; op < 4; op++) {
        unsigned int lo[4], hi[4];
#pragma unroll
        for (int p = 0; p < 4; p++) {
            asm("mov.b64 {%0, %1}, %2;" : "=r"(lo[p]), "=r"(hi[p]) : "l"(acc[op][p]));
        }
        const int o = og * 8 + 2 * op;
        float4 v0, v1;
        v0.x = __uint_as_float(lo[0]); v0.y = __uint_as_float(lo[1]);
        v0.z = __uint_as_float(lo[2]); v0.w = __uint_as_float(lo[3]);
        v1.x = __uint_as_float(hi[0]); v1.y = __uint_as_float(hi[1]);
        v1.z = __uint_as_float(hi[2]); v1.w = __uint_as_float(hi[3]);
        *(float4*)(out + (size_t)o * LL + lbase + lane * 4) = v0;
        *(float4*)(out + (size_t)(o + 1) * LL + lbase + lane * 4) = v1;
    }
}

extern "C" void kernel_launch(void* const* d_in, const int* in_sizes, int n_in,
                              void* d_out, int out_size) {
    const float* x    = (const float*)d_in[0];  // (1, C, S, S)
    const float* w    = (const float*)d_in[1];  // (1, C*9, L)
    const float* conv = (const float*)d_in[2];  // (C, CO)
    float* out = (float*)d_out;                 // (1, CO, S, S)

    reverb_gather_kernel<<<(Cc * LL / 4) / 256, 256>>>(x, w);
    reverb_mix_kernel<<<LL / 128, 256>>>(conv, out);
}